// round 3
// baseline (speedup 1.0000x reference)
#include <cuda_runtime.h>
#include <cuda_bf16.h>
#include <math.h>

// ---------------------------------------------------------------------------
// Problem constants
// ---------------------------------------------------------------------------
#define BB 2
#define SS 2048
#define DD 1024
#define HH 16
#define FF 4096
#define LL 3
#define DK 64
#define MM (BB*SS)          // 4096 rows

// ---------------------------------------------------------------------------
// Scratch (device globals: the sanctioned alternative to cudaMalloc)
// ---------------------------------------------------------------------------
__device__ float g_x  [MM*DD];   // residual stream
__device__ float g_h  [MM*DD];   // LN output / GEMM input
__device__ float g_q  [MM*DD];
__device__ float g_k  [MM*DD];
__device__ float g_v  [MM*DD];
__device__ float g_o  [MM*DD];   // attention output
__device__ float g_mid[MM*FF];   // FFN intermediate

// ---------------------------------------------------------------------------
// Embedding + positional encoding:  x = emb[tok]*sqrt(D) + pe[s]
// ---------------------------------------------------------------------------
__global__ __launch_bounds__(256) void embed_kernel(
    const int* __restrict__ tokens, const float* __restrict__ emb,
    const float* __restrict__ pe)
{
    int idx = blockIdx.x * 256 + threadIdx.x;      // over MM*DD = 4M
    int bs  = idx >> 10;                            // row
    int d   = idx & 1023;
    int tok = tokens[bs];
    int s   = bs & (SS - 1);
    g_x[idx] = emb[tok * DD + d] * 32.0f + pe[s * DD + d];
}

// ---------------------------------------------------------------------------
// LayerNorm, torch semantics: std uses Bessel (n-1), eps added to std.
// One block per row (1024 cols, 256 threads, float4 per thread).
// ---------------------------------------------------------------------------
__global__ __launch_bounds__(256) void ln_kernel(
    const float* __restrict__ src, float* __restrict__ dst,
    const float* __restrict__ ga, const float* __restrict__ gb)
{
    __shared__ float red[8];
    __shared__ float bval;
    int row = blockIdx.x, tid = threadIdx.x;
    float4 v = ((const float4*)(src + row * DD))[tid];

    float s = v.x + v.y + v.z + v.w;
    #pragma unroll
    for (int off = 16; off; off >>= 1) s += __shfl_xor_sync(0xffffffffu, s, off);
    if ((tid & 31) == 0) red[tid >> 5] = s;
    __syncthreads();
    if (tid == 0) {
        float t = 0.f;
        #pragma unroll
        for (int i = 0; i < 8; i++) t += red[i];
        bval = t * (1.0f / DD);
    }
    __syncthreads();
    float mean = bval;

    float dx = v.x - mean, dy = v.y - mean, dz = v.z - mean, dw = v.w - mean;
    float sq = dx*dx + dy*dy + dz*dz + dw*dw;
    #pragma unroll
    for (int off = 16; off; off >>= 1) sq += __shfl_xor_sync(0xffffffffu, sq, off);
    if ((tid & 31) == 0) red[tid >> 5] = sq;
    __syncthreads();
    if (tid == 0) {
        float t = 0.f;
        #pragma unroll
        for (int i = 0; i < 8; i++) t += red[i];
        bval = t;
    }
    __syncthreads();
    float stdv = sqrtf(bval * (1.0f / (DD - 1)));
    float inv  = 1.0f / (stdv + 1e-6f);

    int c = tid * 4;
    float4 o;
    o.x = ga[c + 0] * dx * inv + gb[c + 0];
    o.y = ga[c + 1] * dy * inv + gb[c + 1];
    o.z = ga[c + 2] * dz * inv + gb[c + 2];
    o.w = ga[c + 3] * dw * inv + gb[c + 3];
    ((float4*)(dst + row * DD))[tid] = o;
}

// ---------------------------------------------------------------------------
// SGEMM: C[M,N] = A[M,K] @ B[K,N] + bias[N]  (+relu) (+residual)
// 128x128x8 block, 256 threads, 8x8 microtile (split 4+4). All dims % 128 == 0.
// ---------------------------------------------------------------------------
template<bool RELU, bool RES>
__global__ __launch_bounds__(256) void sgemm_kernel(
    const float* __restrict__ A, const float* __restrict__ B,
    const float* __restrict__ bias, const float* __restrict__ res,
    float* __restrict__ C, int M, int N, int K)
{
    __shared__ float As[8][128];   // transposed A tile: As[k][m]
    __shared__ float Bs[8][128];

    int tid = threadIdx.x;
    int bm = blockIdx.y * 128, bn = blockIdx.x * 128;
    int tx = tid & 15, ty = tid >> 4;

    int arow = tid >> 1, acol = (tid & 1) * 4;     // A: 128 rows x 8 cols
    int brow = tid >> 5, bcol = (tid & 31) * 4;    // B: 8 rows x 128 cols

    const float* Aptr = A + (bm + arow) * K + acol;
    const float* Bptr = B + brow * N + bn + bcol;

    float acc[8][8];
    #pragma unroll
    for (int i = 0; i < 8; i++)
        #pragma unroll
        for (int j = 0; j < 8; j++) acc[i][j] = 0.f;

    for (int k0 = 0; k0 < K; k0 += 8) {
        float4 av = *(const float4*)Aptr;
        float4 bv = *(const float4*)Bptr;
        __syncthreads();                    // previous tile fully consumed
        As[acol + 0][arow] = av.x;
        As[acol + 1][arow] = av.y;
        As[acol + 2][arow] = av.z;
        As[acol + 3][arow] = av.w;
        *(float4*)&Bs[brow][bcol] = bv;
        __syncthreads();
        Aptr += 8;
        Bptr += 8 * N;

        #pragma unroll
        for (int kk = 0; kk < 8; kk++) {
            float4 a0 = *(const float4*)&As[kk][ty * 4];
            float4 a1 = *(const float4*)&As[kk][ty * 4 + 64];
            float4 b0 = *(const float4*)&Bs[kk][tx * 4];
            float4 b1 = *(const float4*)&Bs[kk][tx * 4 + 64];
            float ar[8] = {a0.x, a0.y, a0.z, a0.w, a1.x, a1.y, a1.z, a1.w};
            float br[8] = {b0.x, b0.y, b0.z, b0.w, b1.x, b1.y, b1.z, b1.w};
            #pragma unroll
            for (int i = 0; i < 8; i++)
                #pragma unroll
                for (int j = 0; j < 8; j++)
                    acc[i][j] += ar[i] * br[j];
        }
    }

    #pragma unroll
    for (int ri = 0; ri < 8; ri++) {
        int row = bm + ((ri >> 2) << 6) + ty * 4 + (ri & 3);
        float* crow = C + (size_t)row * N;
        const float* rrow = RES ? (res + (size_t)row * N) : nullptr;
        #pragma unroll
        for (int ci = 0; ci < 8; ci++) {
            int col = bn + ((ci >> 2) << 6) + tx * 4 + (ci & 3);
            float vv = acc[ri][ci] + bias[col];
            if (RELU) vv = fmaxf(vv, 0.f);
            if (RES)  vv += rrow[col];
            crow[col] = vv;
        }
    }
}

// ---------------------------------------------------------------------------
// Flash attention (fp32, online softmax). One block = (b,h, 64-query tile).
// 256 threads = 16x16; each thread owns a 4x4 patch of the 64x64 score tile
// and a 4x4 patch of the 64x64 output tile. K-tile smem is reused for P.
// Exactly 48 KB static smem.
// ---------------------------------------------------------------------------
__global__ __launch_bounds__(256) void attn_kernel(const int* __restrict__ mask)
{
    __shared__ float Qs [64 * 64];   // Qs[r][d]
    __shared__ float KPs[64 * 64];   // first Kt[d][c], then P[r][c]
    __shared__ float Vs [64 * 64];   // Vs[c][d]

    int tid = threadIdx.x;
    int tx = tid & 15, ty = tid >> 4;
    int b = blockIdx.y >> 4;
    int h = blockIdx.y & 15;
    int qt = blockIdx.x;

    int base_q = (b * SS + qt * 64) * DD + h * 64;
    for (int idx = tid; idx < 4096; idx += 256) {
        int r = idx >> 6, d = idx & 63;
        Qs[idx] = g_q[base_q + r * DD + d];
    }

    float m[4], l[4], o[4][4];
    #pragma unroll
    for (int i = 0; i < 4; i++) {
        m[i] = -1e30f; l[i] = 0.f;
        #pragma unroll
        for (int j = 0; j < 4; j++) o[i][j] = 0.f;
    }

    for (int kt = 0; kt < SS / 64; kt++) {
        __syncthreads();   // prev iter done with KPs/Vs (and Qs visible on kt==0)
        int base_k = (b * SS + kt * 64) * DD + h * 64;
        for (int idx = tid; idx < 4096; idx += 256) {
            int c = idx >> 6, d = idx & 63;
            KPs[d * 64 + c] = g_k[base_k + c * DD + d];   // transposed
            Vs[idx]         = g_v[base_k + c * DD + d];
        }
        __syncthreads();

        // s[i][j] = sum_d Q[r_i][d] * K[c_j][d]
        float s[4][4];
        #pragma unroll
        for (int i = 0; i < 4; i++)
            #pragma unroll
            for (int j = 0; j < 4; j++) s[i][j] = 0.f;
        #pragma unroll 16
        for (int d = 0; d < 64; d++) {
            float qv[4];
            #pragma unroll
            for (int i = 0; i < 4; i++) qv[i] = Qs[(ty * 4 + i) * 64 + d];
            float4 kv = *(const float4*)&KPs[d * 64 + tx * 4];
            float kr[4] = {kv.x, kv.y, kv.z, kv.w};
            #pragma unroll
            for (int i = 0; i < 4; i++)
                #pragma unroll
                for (int j = 0; j < 4; j++)
                    s[i][j] += qv[i] * kr[j];
        }

        // scale + mask
        int mbase = b * SS + kt * 64 + tx * 4;
        #pragma unroll
        for (int j = 0; j < 4; j++) {
            int mv = mask[mbase + j];
            #pragma unroll
            for (int i = 0; i < 4; i++)
                s[i][j] = mv ? s[i][j] * 0.125f : -1e9f;
        }

        // row max (reduce over the 16 tx lanes of each half-warp)
        float nm[4], alpha[4], p[4][4], rs[4];
        #pragma unroll
        for (int i = 0; i < 4; i++) {
            float tm = fmaxf(fmaxf(s[i][0], s[i][1]), fmaxf(s[i][2], s[i][3]));
            #pragma unroll
            for (int off = 8; off; off >>= 1)
                tm = fmaxf(tm, __shfl_xor_sync(0xffffffffu, tm, off, 16));
            nm[i] = fmaxf(m[i], tm);
            alpha[i] = __expf(m[i] - nm[i]);
            m[i] = nm[i];
        }
        #pragma unroll
        for (int i = 0; i < 4; i++) {
            float rsum = 0.f;
            #pragma unroll
            for (int j = 0; j < 4; j++) {
                p[i][j] = __expf(s[i][j] - nm[i]);
                rsum += p[i][j];
            }
            #pragma unroll
            for (int off = 8; off; off >>= 1)
                rsum += __shfl_xor_sync(0xffffffffu, rsum, off, 16);
            rs[i] = rsum;
        }
        #pragma unroll
        for (int i = 0; i < 4; i++) {
            l[i] = l[i] * alpha[i] + rs[i];
            #pragma unroll
            for (int j = 0; j < 4; j++) o[i][j] *= alpha[i];
        }

        __syncthreads();   // everyone done reading Kt before P overwrites it
        #pragma unroll
        for (int i = 0; i < 4; i++)
            *(float4*)&KPs[(ty * 4 + i) * 64 + tx * 4] =
                make_float4(p[i][0], p[i][1], p[i][2], p[i][3]);
        __syncthreads();

        // o[i][j] += sum_c P[r_i][c] * V[c][dk_j]
        #pragma unroll 16
        for (int c = 0; c < 64; c++) {
            float pv[4];
            #pragma unroll
            for (int i = 0; i < 4; i++) pv[i] = KPs[(ty * 4 + i) * 64 + c];
            float4 vv = *(const float4*)&Vs[c * 64 + tx * 4];
            float vr[4] = {vv.x, vv.y, vv.z, vv.w};
            #pragma unroll
            for (int i = 0; i < 4; i++)
                #pragma unroll
                for (int j = 0; j < 4; j++)
                    o[i][j] += pv[i] * vr[j];
        }
    }

    int base_o = (b * SS + qt * 64) * DD + h * 64;
    #pragma unroll
    for (int i = 0; i < 4; i++) {
        float inv = 1.0f / l[i];
        #pragma unroll
        for (int j = 0; j < 4; j++)
            g_o[base_o + (ty * 4 + i) * DD + tx * 4 + j] = o[i][j] * inv;
    }
}

// ---------------------------------------------------------------------------
// Launch
// ---------------------------------------------------------------------------
extern "C" void kernel_launch(void* const* d_in, const int* in_sizes, int n_in,
                              void* d_out, int out_size)
{
    (void)in_sizes; (void)n_in; (void)out_size;
    const int*   tokens = (const int*)  d_in[0];
    const int*   mask   = (const int*)  d_in[1];
    const float* emb    = (const float*)d_in[2];
    const float* pe     = (const float*)d_in[3];
    const float* Wq     = (const float*)d_in[4];
    const float* bq     = (const float*)d_in[5];
    const float* Wk     = (const float*)d_in[6];
    const float* bk     = (const float*)d_in[7];
    const float* Wv     = (const float*)d_in[8];
    const float* bv     = (const float*)d_in[9];
    const float* Wo     = (const float*)d_in[10];
    const float* bo     = (const float*)d_in[11];
    const float* w1     = (const float*)d_in[12];
    const float* b1     = (const float*)d_in[13];
    const float* w2     = (const float*)d_in[14];
    const float* b2     = (const float*)d_in[15];
    const float* ln_a   = (const float*)d_in[16];
    const float* ln_b   = (const float*)d_in[17];
    const float* fa     = (const float*)d_in[18];
    const float* fb     = (const float*)d_in[19];
    float* out = (float*)d_out;

    float *px, *ph, *pq, *pk, *pv, *po, *pmid;
    cudaGetSymbolAddress((void**)&px,   g_x);
    cudaGetSymbolAddress((void**)&ph,   g_h);
    cudaGetSymbolAddress((void**)&pq,   g_q);
    cudaGetSymbolAddress((void**)&pk,   g_k);
    cudaGetSymbolAddress((void**)&pv,   g_v);
    cudaGetSymbolAddress((void**)&po,   g_o);
    cudaGetSymbolAddress((void**)&pmid, g_mid);

    embed_kernel<<<(MM * DD) / 256, 256>>>(tokens, emb, pe);

    dim3 gD(DD / 128, MM / 128);   // N=1024 output GEMMs
    dim3 gF(FF / 128, MM / 128);   // N=4096 output GEMMs

    for (int l = 0; l < LL; l++) {
        const float* lnA = ln_a + l * 2 * DD;
        const float* lnB = ln_b + l * 2 * DD;

        // --- attention sublayer ---
        ln_kernel<<<MM, 256>>>(px, ph, lnA, lnB);
        sgemm_kernel<false, false><<<gD, 256>>>(ph, Wq + l * DD * DD, bq + l * DD,
                                                nullptr, pq, MM, DD, DD);
        sgemm_kernel<false, false><<<gD, 256>>>(ph, Wk + l * DD * DD, bk + l * DD,
                                                nullptr, pk, MM, DD, DD);
        sgemm_kernel<false, false><<<gD, 256>>>(ph, Wv + l * DD * DD, bv + l * DD,
                                                nullptr, pv, MM, DD, DD);
        attn_kernel<<<dim3(SS / 64, BB * HH), 256>>>(mask);
        sgemm_kernel<false, true><<<gD, 256>>>(po, Wo + l * DD * DD, bo + l * DD,
                                               px, px, MM, DD, DD);

        // --- FFN sublayer ---
        ln_kernel<<<MM, 256>>>(px, ph, lnA + DD, lnB + DD);
        sgemm_kernel<true, false><<<gF, 256>>>(ph, w1 + l * DD * FF, b1 + l * FF,
                                               nullptr, pmid, MM, FF, DD);
        sgemm_kernel<false, true><<<gD, 256>>>(pmid, w2 + l * FF * DD, b2 + l * DD,
                                               px, px, MM, DD, FF);
    }

    ln_kernel<<<MM, 256>>>(px, out, fa, fb);
}